// round 11
// baseline (speedup 1.0000x reference)
#include <cuda_runtime.h>
#include <cuda_fp16.h>
#include <cstdint>

// Problem constants (B=2, S=1024, H=32, KVH=8, HD=128, DM=4096)
#define T_TOK   2048
#define DMODEL  4096
#define QKVC    6144
#define NH      32
#define NKV     8
#define HDIM    128
#define SEQ     1024
#define NBATCH  2
#define QSCALE  0.08838834764831845f

__device__ float g_qkv[(size_t)T_TOK * QKVC];
__device__ uint32_t g_pa[(size_t)T_TOK * DMODEL / 2];   // packed fp16 A tiles
__device__ uint32_t g_pb[(size_t)QKVC * DMODEL / 2];    // packed fp16 W tiles

__device__ __forceinline__ uint32_t pack_h2(float lo, float hi) {
    __half2 h = __floats2half2_rn(lo, hi);
    return *reinterpret_cast<uint32_t*>(&h);
}

#define MMA_F16(d, a, b)                                                      \
    asm volatile(                                                             \
        "mma.sync.aligned.m16n8k16.row.col.f32.f16.f16.f32 "                  \
        "{%0,%1,%2,%3},{%4,%5,%6,%7},{%8,%9},{%0,%1,%2,%3};"                  \
        : "+f"(d[0]), "+f"(d[1]), "+f"(d[2]), "+f"(d[3])                      \
        : "r"(a[0]), "r"(a[1]), "r"(a[2]), "r"(a[3]), "r"(b[0]), "r"(b[1]))

__device__ __forceinline__ void cp_async16(uint32_t smem_addr, const void* gptr) {
    asm volatile("cp.async.cg.shared.global [%0], [%1], 16;"
                 :: "r"(smem_addr), "l"(gptr) : "memory");
}
#define CP_COMMIT() asm volatile("cp.async.commit_group;" ::: "memory")
#define CP_WAIT3()  asm volatile("cp.async.wait_group 3;" ::: "memory")

// ---------------------------------------------------------------------------
// Kernel 0: fused pack. Blocks [0, 8192) pack A; blocks [8192, 20480) pack W.
// Layout formulas identical to R9/R10 (verified).
// ---------------------------------------------------------------------------
#define PACKA_BLOCKS 8192
#define PACKW_BLOCKS 12288

__global__ __launch_bounds__(256) void pack_kernel(const float* __restrict__ A,
                                                   const float* __restrict__ W) {
    if (blockIdx.x < PACKA_BLOCKS) {
        int i = blockIdx.x * 256 + threadIdx.x;
        int r  = i >> 10;
        int k0 = (i & 1023) << 2;
        float4 v = *reinterpret_cast<const float4*>(A + (size_t)r * DMODEL + k0);

        int mTile = r >> 7, rLoc = r & 127;
        int kTile = k0 >> 4, kLoc = k0 & 15;
        uint32_t* dst = g_pa + ((size_t)(mTile * (DMODEL / 16) + kTile)) * 1024;

        int rb = rLoc >> 4, r16 = rLoc & 15;
        int reg = ((kLoc >= 8) ? 2 : 0) + ((r16 >= 8) ? 1 : 0);
        int lane0 = (r16 & 7) * 4 + ((kLoc >> 1) & 3);
        int base = rb * 128;
        dst[base + lane0 * 4 + reg]       = pack_h2(v.x, v.y);
        dst[base + (lane0 + 1) * 4 + reg] = pack_h2(v.z, v.w);
    } else {
        int i = (blockIdx.x - PACKA_BLOCKS) * 256 + threadIdx.x;
        int kp = i / 1536;
        int n0 = (i - kp * 1536) << 2;
        int k  = kp * 2;
        float4 vlo = *reinterpret_cast<const float4*>(W + (size_t)k * QKVC + n0);
        float4 vhi = *reinterpret_cast<const float4*>(W + (size_t)(k + 1) * QKVC + n0);

        int nTile = n0 >> 7, nLoc0 = n0 & 127;
        int kTile = k >> 4,  kLoc  = k & 15;
        uint32_t* dst = g_pb + ((size_t)(nTile * (DMODEL / 16) + kTile)) * 1024;

        int tig = (kLoc >> 1) & 3;
        int reg = (kLoc >= 8) ? 1 : 0;
        float lo[4] = {vlo.x, vlo.y, vlo.z, vlo.w};
        float hi[4] = {vhi.x, vhi.y, vhi.z, vhi.w};
#pragma unroll
        for (int j = 0; j < 4; j++) {
            int n = nLoc0 + j;
            int nblk = n >> 3, nn = n & 7;
            dst[nblk * 64 + (nn * 4 + tig) * 2 + reg] = pack_h2(lo[j], hi[j]);
        }
    }
}

// ---------------------------------------------------------------------------
// Kernel 1: QKV GEMM, fp16 m16n8k16, pre-packed operands.
// CTA 128x128, 256 threads (8 warps 2x4), warp tile 64x32.
// BK=32 chunk = 2 ktiles; stage = 16KB; FIVE stages = 80KB; wait_group 3.
// ---------------------------------------------------------------------------
__global__ __launch_bounds__(256, 2) void gemm_f16_kernel() {
    extern __shared__ __align__(16) uint32_t smem[];   // 5 * 4096 words

    const int tid  = threadIdx.x;
    const int wid  = tid >> 5;
    const int lane = tid & 31;
    const int gid  = lane >> 2;
    const int tig  = lane & 3;
    const int wm   = wid >> 2;
    const int wn   = wid & 3;

    const uint32_t smem_base = (uint32_t)__cvta_generic_to_shared(smem);
    const uint32_t* pa = g_pa + (size_t)blockIdx.y * (DMODEL / 16) * 1024;
    const uint32_t* pb = g_pb + (size_t)blockIdx.x * (DMODEL / 16) * 1024;

    const int NCH = DMODEL / 32;   // 128 BK32 chunks

    // Stage layout (words): [A kt0 1024][A kt1 1024][B kt0 1024][B kt1 1024]
#define ISSUE(ch, s)                                                           \
    do {                                                                       \
        uint32_t sa = smem_base + (uint32_t)(s) * 16384;                       \
        const uint32_t* gA = pa + (size_t)(ch) * 2048 + tid * 4;               \
        const uint32_t* gB = pb + (size_t)(ch) * 2048 + tid * 4;               \
        cp_async16(sa + tid * 16,          gA);                                \
        cp_async16(sa + tid * 16 + 4096,   gA + 1024);                         \
        cp_async16(sa + 8192 + tid * 16,        gB);                           \
        cp_async16(sa + 8192 + tid * 16 + 4096, gB + 1024);                    \
    } while (0)

    float acc[4][4][4];
#pragma unroll
    for (int i = 0; i < 4; i++)
#pragma unroll
        for (int j = 0; j < 4; j++)
#pragma unroll
            for (int c = 0; c < 4; c++) acc[i][j][c] = 0.f;

    // Prologue: 4 chunks in flight.
    ISSUE(0, 0); CP_COMMIT();
    ISSUE(1, 1); CP_COMMIT();
    ISSUE(2, 2); CP_COMMIT();
    ISSUE(3, 3); CP_COMMIT();
    CP_WAIT3();            // chunk 0 resident
    __syncthreads();

    for (int ch = 0; ch < NCH; ch++) {
        if (ch + 4 < NCH) ISSUE(ch + 4, (ch + 4) % 5);
        CP_COMMIT();

        const uint32_t* St = smem + (size_t)(ch % 5) * 4096;

#pragma unroll
        for (int kt = 0; kt < 2; kt++) {
            const uint32_t* As = St + kt * 1024;
            const uint32_t* Bs = St + 2048 + kt * 1024;
            uint4 av[4];
            uint2 bv[4];
#pragma unroll
            for (int i = 0; i < 4; i++)
                av[i] = *reinterpret_cast<const uint4*>(
                    &As[((wm << 2) + i) * 128 + (lane << 2)]);
#pragma unroll
            for (int j = 0; j < 4; j++)
                bv[j] = *reinterpret_cast<const uint2*>(
                    &Bs[((wn << 2) + j) * 64 + (lane << 1)]);
#pragma unroll
            for (int i = 0; i < 4; i++)
#pragma unroll
                for (int j = 0; j < 4; j++)
                    MMA_F16(acc[i][j], (reinterpret_cast<uint32_t*>(&av[i])),
                            (reinterpret_cast<uint32_t*>(&bv[j])));
        }

        CP_WAIT3();        // next chunk resident
        __syncthreads();
    }

    float* C = g_qkv + (size_t)blockIdx.y * 128 * QKVC + blockIdx.x * 128;
#pragma unroll
    for (int i = 0; i < 4; i++) {
#pragma unroll
        for (int j = 0; j < 4; j++) {
            int r = wm * 64 + i * 16 + gid;
            int c = wn * 32 + j * 8 + 2 * tig;
            float2 v0 = {acc[i][j][0], acc[i][j][1]};
            float2 v1 = {acc[i][j][2], acc[i][j][3]};
            *reinterpret_cast<float2*>(C + (size_t)(r)     * QKVC + c) = v0;
            *reinterpret_cast<float2*>(C + (size_t)(r + 8) * QKVC + c) = v1;
        }
    }
}

// ---------------------------------------------------------------------------
// Kernel 2: RoPE in-place (q scaled by 1/sqrt(HD)).
// ---------------------------------------------------------------------------
__global__ __launch_bounds__(256) void rope_kernel(const float* __restrict__ cosT,
                                                   const float* __restrict__ sinT) {
    int idx = blockIdx.x * 256 + threadIdx.x;
    int d    = idx & 63;
    int head = (idx >> 6) % 40;
    int t    = idx / (64 * 40);

    float c = cosT[t * HDIM + d];
    float s = sinT[t * HDIM + d];

    float* p = g_qkv + (size_t)t * QKVC + head * HDIM;
    float x1 = p[d];
    float x2 = p[d + 64];
    float o1 = x1 * c - x2 * s;
    float o2 = x2 * c + x1 * s;
    if (head < NH) { o1 *= QSCALE; o2 *= QSCALE; }
    p[d]      = o1;
    p[d + 64] = o2;
}

// ---------------------------------------------------------------------------
// Kernel 3: fp16 tensor-core flash attention (causal, GQA n_rep=4).
// Longest-first CTA ordering to shape the tail wave.
// ---------------------------------------------------------------------------
#define AQ_WORDS (8 * 1032)
#define AK_WORDS (8 * 520)
#define AV_WORDS (4 * 1032)
#define AP_WORDS (128 * 36)
#define ATTN_SMEM ((AQ_WORDS + AK_WORDS + AV_WORDS + AP_WORDS) * 4)  // 84608

__global__ __launch_bounds__(256) void attn_tc_kernel(float* __restrict__ out) {
    extern __shared__ __align__(16) uint32_t sm[];
    uint32_t* Qs = sm;
    uint32_t* Ks = Qs + AQ_WORDS;
    uint32_t* Vs = Ks + AK_WORDS;
    uint32_t* Ps = Vs + AV_WORDS;

    const int tid  = threadIdx.x;
    const int wid  = tid >> 5;
    const int lane = tid & 31;
    const int gid  = lane >> 2;
    const int tig  = lane & 3;
    const int qrow = wid * 16;

    const int b   = blockIdx.y >> 5;
    const int h   = blockIdx.y & 31;
    const int kvh = h >> 2;
    const int qblk = (SEQ / 128 - 1) - blockIdx.x;   // longest-first
    const int q0  = qblk * 128;

    const float* Qg = g_qkv + (size_t)(b * SEQ + q0) * QKVC + h * HDIM;
    const float* Kg = g_qkv + (size_t)(b * SEQ) * QKVC + NH * HDIM + kvh * HDIM;
    const float* Vg = Kg + NKV * HDIM;

    // Load Q tile 128x128 into A-frag layout (fp16).
#pragma unroll
    for (int i = 0; i < 16; i++) {
        int idx = tid + i * 256;
        int r = idx >> 5;
        int c = (idx & 31) << 2;
        float4 v = *reinterpret_cast<const float4*>(Qg + (size_t)r * QKVC + c);
        int kTile = c >> 4, kLoc = c & 15;
        int rb = r >> 4, r16 = r & 15;
        int reg = ((kLoc >= 8) ? 2 : 0) + ((r16 >= 8) ? 1 : 0);
        int lane0 = (r16 & 7) * 4 + ((kLoc >> 1) & 3);
        uint32_t* d = &Qs[kTile * 1032 + rb * 128];
        d[lane0 * 4 + reg]       = pack_h2(v.x, v.y);
        d[(lane0 + 1) * 4 + reg] = pack_h2(v.z, v.w);
    }

    float m[2] = {-1e30f, -1e30f}, l[2] = {0.f, 0.f};
    float oacc[16][4];
#pragma unroll
    for (int nb = 0; nb < 16; nb++)
#pragma unroll
        for (int c = 0; c < 4; c++) oacc[nb][c] = 0.f;

    const int ktiles = 2 * (qblk + 1);
    for (int kt = 0; kt < ktiles; kt++) {
        const int kv0 = kt * 64;
        __syncthreads();

        // K tile 64x128 -> B-frag layout (n=kv, k=d).
#pragma unroll
        for (int i = 0; i < 8; i++) {
            int idx = tid + i * 256;
            int r = idx >> 5;
            int c = (idx & 31) << 2;
            float4 v = *reinterpret_cast<const float4*>(Kg + (size_t)(kv0 + r) * QKVC + c);
            int kTile = c >> 4, kLoc = c & 15;
            int tig0 = (kLoc >> 1) & 3;
            int reg = (kLoc >= 8) ? 1 : 0;
            int nblk = r >> 3, nn = r & 7;
            uint32_t* d = &Ks[kTile * 520 + nblk * 64];
            d[(nn * 4 + tig0) * 2 + reg]     = pack_h2(v.x, v.y);
            d[(nn * 4 + tig0 + 1) * 2 + reg] = pack_h2(v.z, v.w);
        }
        // V tile 64x128 -> B-frag layout (n=d, k=kv).
#pragma unroll
        for (int i = 0; i < 4; i++) {
            int idx = tid + i * 256;
            int kvp = idx >> 5;
            int d0  = (idx & 31) << 2;
            int kv  = kvp * 2;
            float4 vlo = *reinterpret_cast<const float4*>(Vg + (size_t)(kv0 + kv) * QKVC + d0);
            float4 vhi = *reinterpret_cast<const float4*>(Vg + (size_t)(kv0 + kv + 1) * QKVC + d0);
            int kTile = kv >> 4, kLoc = kv & 15;
            int tg = (kLoc >> 1) & 3;
            int reg = (kLoc >= 8) ? 1 : 0;
            float lo[4] = {vlo.x, vlo.y, vlo.z, vlo.w};
            float hi[4] = {vhi.x, vhi.y, vhi.z, vhi.w};
            uint32_t* dst = &Vs[kTile * 1032];
#pragma unroll
            for (int j = 0; j < 4; j++) {
                int dd = d0 + j;
                int nblk = dd >> 3, nn = dd & 7;
                dst[nblk * 64 + (nn * 4 + tg) * 2 + reg] = pack_h2(lo[j], hi[j]);
            }
        }
        __syncthreads();

        // ---- S = Q K^T ----
        float sacc[8][4];
#pragma unroll
        for (int nb = 0; nb < 8; nb++)
#pragma unroll
            for (int c = 0; c < 4; c++) sacc[nb][c] = 0.f;

#pragma unroll
        for (int ks = 0; ks < 8; ks++) {
            uint4 av = *reinterpret_cast<const uint4*>(
                &Qs[ks * 1032 + wid * 128 + (lane << 2)]);
#pragma unroll
            for (int nb = 0; nb < 8; nb++) {
                uint2 bb = *reinterpret_cast<const uint2*>(
                    &Ks[ks * 520 + nb * 64 + (lane << 1)]);
                MMA_F16(sacc[nb], (reinterpret_cast<uint32_t*>(&av)),
                        (reinterpret_cast<uint32_t*>(&bb)));
            }
        }

        // Causal mask.
        const int row0 = q0 + qrow + gid;
        const int row1 = row0 + 8;
        if (kv0 + 63 > row0) {
#pragma unroll
            for (int nb = 0; nb < 8; nb++) {
                int c0 = kv0 + nb * 8 + 2 * tig;
                if (c0 > row0)     sacc[nb][0] = -1e30f;
                if (c0 + 1 > row0) sacc[nb][1] = -1e30f;
                if (c0 > row1)     sacc[nb][2] = -1e30f;
                if (c0 + 1 > row1) sacc[nb][3] = -1e30f;
            }
        }

        // ---- online softmax ----
#pragma unroll
        for (int r = 0; r < 2; r++) {
            float rmax = -1e30f;
#pragma unroll
            for (int nb = 0; nb < 8; nb++)
                rmax = fmaxf(rmax, fmaxf(sacc[nb][2 * r], sacc[nb][2 * r + 1]));
            rmax = fmaxf(rmax, __shfl_xor_sync(0xffffffffu, rmax, 1));
            rmax = fmaxf(rmax, __shfl_xor_sync(0xffffffffu, rmax, 2));
            float nm = fmaxf(m[r], rmax);
            float corr = __expf(m[r] - nm);
            float rs = 0.f;
#pragma unroll
            for (int nb = 0; nb < 8; nb++) {
                float p0 = __expf(sacc[nb][2 * r]     - nm);
                float p1 = __expf(sacc[nb][2 * r + 1] - nm);
                sacc[nb][2 * r] = p0; sacc[nb][2 * r + 1] = p1;
                rs += p0 + p1;
            }
            rs += __shfl_xor_sync(0xffffffffu, rs, 1);
            rs += __shfl_xor_sync(0xffffffffu, rs, 2);
            m[r] = nm;
            l[r] = l[r] * corr + rs;
#pragma unroll
            for (int nb = 0; nb < 16; nb++) {
                oacc[nb][2 * r]     *= corr;
                oacc[nb][2 * r + 1] *= corr;
            }
        }

        // Store P as half2 words.
#pragma unroll
        for (int nb = 0; nb < 8; nb++) {
            Ps[(qrow + gid)     * 36 + nb * 4 + tig] = pack_h2(sacc[nb][0], sacc[nb][1]);
            Ps[(qrow + gid + 8) * 36 + nb * 4 + tig] = pack_h2(sacc[nb][2], sacc[nb][3]);
        }

        // ---- O += P V ----
#pragma unroll
        for (int kb = 0; kb < 4; kb++) {
            uint32_t a[4];
            a[0] = Ps[(qrow + gid)     * 36 + kb * 8 + tig];
            a[1] = Ps[(qrow + gid + 8) * 36 + kb * 8 + tig];
            a[2] = Ps[(qrow + gid)     * 36 + kb * 8 + tig + 4];
            a[3] = Ps[(qrow + gid + 8) * 36 + kb * 8 + tig + 4];
#pragma unroll
            for (int nb = 0; nb < 16; nb++) {
                uint2 bb = *reinterpret_cast<const uint2*>(
                    &Vs[kb * 1032 + nb * 64 + (lane << 1)]);
                MMA_F16(oacc[nb], a, (reinterpret_cast<uint32_t*>(&bb)));
            }
        }
    }

    // Epilogue.
    const float inv0 = 1.f / l[0];
    const float inv1 = 1.f / l[1];
    const int t0 = b * SEQ + q0 + qrow + gid;
#pragma unroll
    for (int nb = 0; nb < 16; nb++) {
        int c = nb * 8 + 2 * tig;
        float2 v0 = {oacc[nb][0] * inv0, oacc[nb][1] * inv0};
        float2 v1 = {oacc[nb][2] * inv1, oacc[nb][3] * inv1};
        *reinterpret_cast<float2*>(out + (size_t)t0 * (NH * HDIM) + h * HDIM + c) = v0;
        *reinterpret_cast<float2*>(out + (size_t)(t0 + 8) * (NH * HDIM) + h * HDIM + c) = v1;
    }
}

// ---------------------------------------------------------------------------
extern "C" void kernel_launch(void* const* d_in, const int* in_sizes, int n_in,
                              void* d_out, int out_size) {
    const float* hidden = (const float*)d_in[0];
    const float* w_qkv  = (const float*)d_in[1];
    const float* cosT   = (const float*)d_in[2];
    const float* sinT   = (const float*)d_in[3];
    float* out = (float*)d_out;

    cudaFuncSetAttribute(gemm_f16_kernel, cudaFuncAttributeMaxDynamicSharedMemorySize, 81920);
    cudaFuncSetAttribute(attn_tc_kernel, cudaFuncAttributeMaxDynamicSharedMemorySize, ATTN_SMEM);

    pack_kernel<<<PACKA_BLOCKS + PACKW_BLOCKS, 256>>>(hidden, w_qkv);

    dim3 ggrid(QKVC / 128, T_TOK / 128);   // (48, 16)
    gemm_f16_kernel<<<ggrid, 256, 81920>>>();

    int rope_threads = T_TOK * (NH + NKV) * 64;
    rope_kernel<<<rope_threads / 256, 256>>>(cosT, sinT);

    dim3 agrid(SEQ / 128, NBATCH * NH);    // (8, 64)
    attn_tc_kernel<<<agrid, 256, ATTN_SMEM>>>(out);
}

// round 12
// speedup vs baseline: 1.3361x; 1.3361x over previous
#include <cuda_runtime.h>
#include <cuda_fp16.h>
#include <cstdint>

// Problem constants (B=2, S=1024, H=32, KVH=8, HD=128, DM=4096)
#define T_TOK   2048
#define DMODEL  4096
#define QKVC    6144
#define NH      32
#define NKV     8
#define HDIM    128
#define SEQ     1024
#define NBATCH  2
#define QSCALE  0.08838834764831845f

__device__ float g_qkv[(size_t)T_TOK * QKVC];
__device__ uint32_t g_pa[(size_t)T_TOK * DMODEL / 2];   // packed fp16 A tiles (GEMM)
__device__ uint32_t g_pb[(size_t)QKVC * DMODEL / 2];    // packed fp16 W tiles (GEMM)
__device__ uint32_t g_pq[(size_t)T_TOK * NH * HDIM / 2];   // Q A-frag tiles (post-rope)
__device__ uint32_t g_pk[(size_t)T_TOK * NKV * HDIM / 2];  // K B-frag tiles (post-rope)
__device__ uint32_t g_pv[(size_t)T_TOK * NKV * HDIM / 2];  // V B-frag tiles (transposed)

__device__ __forceinline__ uint32_t pack_h2(float lo, float hi) {
    __half2 h = __floats2half2_rn(lo, hi);
    return *reinterpret_cast<uint32_t*>(&h);
}

#define MMA_F16(d, a, b)                                                      \
    asm volatile(                                                             \
        "mma.sync.aligned.m16n8k16.row.col.f32.f16.f16.f32 "                  \
        "{%0,%1,%2,%3},{%4,%5,%6,%7},{%8,%9},{%0,%1,%2,%3};"                  \
        : "+f"(d[0]), "+f"(d[1]), "+f"(d[2]), "+f"(d[3])                      \
        : "r"(a[0]), "r"(a[1]), "r"(a[2]), "r"(a[3]), "r"(b[0]), "r"(b[1]))

__device__ __forceinline__ void cp_async16(uint32_t smem_addr, const void* gptr) {
    asm volatile("cp.async.cg.shared.global [%0], [%1], 16;"
                 :: "r"(smem_addr), "l"(gptr) : "memory");
}
#define CP_COMMIT() asm volatile("cp.async.commit_group;" ::: "memory")
#define CP_WAIT1()  asm volatile("cp.async.wait_group 1;" ::: "memory")

// ---------------------------------------------------------------------------
// Kernel 0a/0b: pack A and W for the GEMM (verified R9/R10 layouts).
// ---------------------------------------------------------------------------
__global__ __launch_bounds__(256) void pack_a_kernel(const float* __restrict__ A) {
    int i = blockIdx.x * 256 + threadIdx.x;
    int r  = i >> 10;
    int k0 = (i & 1023) << 2;
    float4 v = *reinterpret_cast<const float4*>(A + (size_t)r * DMODEL + k0);

    int mTile = r >> 7, rLoc = r & 127;
    int kTile = k0 >> 4, kLoc = k0 & 15;
    uint32_t* dst = g_pa + ((size_t)(mTile * (DMODEL / 16) + kTile)) * 1024;

    int rb = rLoc >> 4, r16 = rLoc & 15;
    int reg = ((kLoc >= 8) ? 2 : 0) + ((r16 >= 8) ? 1 : 0);
    int lane0 = (r16 & 7) * 4 + ((kLoc >> 1) & 3);
    int base = rb * 128;
    dst[base + lane0 * 4 + reg]       = pack_h2(v.x, v.y);
    dst[base + (lane0 + 1) * 4 + reg] = pack_h2(v.z, v.w);
}

__global__ __launch_bounds__(256) void pack_w_kernel(const float* __restrict__ W) {
    int i = blockIdx.x * 256 + threadIdx.x;
    int kp = i / 1536;
    int n0 = (i - kp * 1536) << 2;
    int k  = kp * 2;
    float4 vlo = *reinterpret_cast<const float4*>(W + (size_t)k * QKVC + n0);
    float4 vhi = *reinterpret_cast<const float4*>(W + (size_t)(k + 1) * QKVC + n0);

    int nTile = n0 >> 7, nLoc0 = n0 & 127;
    int kTile = k >> 4,  kLoc  = k & 15;
    uint32_t* dst = g_pb + ((size_t)(nTile * (DMODEL / 16) + kTile)) * 1024;

    int tig = (kLoc >> 1) & 3;
    int reg = (kLoc >= 8) ? 1 : 0;
    float lo[4] = {vlo.x, vlo.y, vlo.z, vlo.w};
    float hi[4] = {vhi.x, vhi.y, vhi.z, vhi.w};
#pragma unroll
    for (int j = 0; j < 4; j++) {
        int n = nLoc0 + j;
        int nblk = n >> 3, nn = n & 7;
        dst[nblk * 64 + (nn * 4 + tig) * 2 + reg] = pack_h2(lo[j], hi[j]);
    }
}

// ---------------------------------------------------------------------------
// Kernel 1: QKV GEMM (R10-proven: fp16 m16n8k16, BK=64, 3 stages, 96KB).
// ---------------------------------------------------------------------------
__global__ __launch_bounds__(256, 2) void gemm_f16_kernel() {
    extern __shared__ __align__(16) uint32_t smem[];

    const int tid  = threadIdx.x;
    const int wid  = tid >> 5;
    const int lane = tid & 31;
    const int gid  = lane >> 2;
    const int tig  = lane & 3;
    const int wm   = wid >> 2;
    const int wn   = wid & 3;

    const uint32_t smem_base = (uint32_t)__cvta_generic_to_shared(smem);
    const uint32_t* pa = g_pa + (size_t)blockIdx.y * (DMODEL / 16) * 1024;
    const uint32_t* pb = g_pb + (size_t)blockIdx.x * (DMODEL / 16) * 1024;

    const int NCH = DMODEL / 64;

#define ISSUE(ch, s)                                                           \
    do {                                                                       \
        uint32_t sa = smem_base + (uint32_t)(s) * 32768;                       \
        const uint32_t* gA = pa + (size_t)(ch) * 4096 + tid * 4;               \
        const uint32_t* gB = pb + (size_t)(ch) * 4096 + tid * 4;               \
        cp_async16(sa + tid * 16,           gA);                               \
        cp_async16(sa + tid * 16 + 4096,    gA + 1024);                        \
        cp_async16(sa + tid * 16 + 8192,    gA + 2048);                        \
        cp_async16(sa + tid * 16 + 12288,   gA + 3072);                        \
        cp_async16(sa + 16384 + tid * 16,         gB);                         \
        cp_async16(sa + 16384 + tid * 16 + 4096,  gB + 1024);                  \
        cp_async16(sa + 16384 + tid * 16 + 8192,  gB + 2048);                  \
        cp_async16(sa + 16384 + tid * 16 + 12288, gB + 3072);                  \
    } while (0)

    float acc[4][4][4];
#pragma unroll
    for (int i = 0; i < 4; i++)
#pragma unroll
        for (int j = 0; j < 4; j++)
#pragma unroll
            for (int c = 0; c < 4; c++) acc[i][j][c] = 0.f;

    ISSUE(0, 0); CP_COMMIT();
    ISSUE(1, 1); CP_COMMIT();
    CP_WAIT1();
    __syncthreads();

    for (int ch = 0; ch < NCH; ch++) {
        if (ch + 2 < NCH) ISSUE(ch + 2, (ch + 2) % 3);
        CP_COMMIT();

        const uint32_t* St = smem + (size_t)(ch % 3) * 8192;

#pragma unroll
        for (int kt = 0; kt < 4; kt++) {
            const uint32_t* As = St + kt * 1024;
            const uint32_t* Bs = St + 4096 + kt * 1024;
            uint4 av[4];
            uint2 bv[4];
#pragma unroll
            for (int i = 0; i < 4; i++)
                av[i] = *reinterpret_cast<const uint4*>(
                    &As[((wm << 2) + i) * 128 + (lane << 2)]);
#pragma unroll
            for (int j = 0; j < 4; j++)
                bv[j] = *reinterpret_cast<const uint2*>(
                    &Bs[((wn << 2) + j) * 64 + (lane << 1)]);
#pragma unroll
            for (int i = 0; i < 4; i++)
#pragma unroll
                for (int j = 0; j < 4; j++)
                    MMA_F16(acc[i][j], (reinterpret_cast<uint32_t*>(&av[i])),
                            (reinterpret_cast<uint32_t*>(&bv[j])));
        }

        CP_WAIT1();
        __syncthreads();
    }

    float* C = g_qkv + (size_t)blockIdx.y * 128 * QKVC + blockIdx.x * 128;
#pragma unroll
    for (int i = 0; i < 4; i++) {
#pragma unroll
        for (int j = 0; j < 4; j++) {
            int r = wm * 64 + i * 16 + gid;
            int c = wn * 32 + j * 8 + 2 * tig;
            float2 v0 = {acc[i][j][0], acc[i][j][1]};
            float2 v1 = {acc[i][j][2], acc[i][j][3]};
            *reinterpret_cast<float2*>(C + (size_t)(r)     * QKVC + c) = v0;
            *reinterpret_cast<float2*>(C + (size_t)(r + 8) * QKVC + c) = v1;
        }
    }
}

// ---------------------------------------------------------------------------
// Kernel 2: RoPE + pack Q (A-frag) / K (B-frag) as fp16.
// Thread handles (t, head, j): dims (2j, 2j+1) and (64+2j, 64+2j+1).
// g_pq layout: [b][qblk(8)][h(32)][ktile(8)][1024]
// g_pk layout: [b][hkv(8)][kvblk(16)][ktile(8)][512]
// ---------------------------------------------------------------------------
__global__ __launch_bounds__(256) void rope_pack_kernel(const float* __restrict__ cosT,
                                                        const float* __restrict__ sinT) {
    int idx = blockIdx.x * 256 + threadIdx.x;      // T_TOK*40*32
    int j    = idx & 31;
    int head = (idx >> 5) % 40;
    int t    = idx / (32 * 40);
    int d0   = 2 * j;

    const float* p = g_qkv + (size_t)t * QKVC + head * HDIM;
    float2 x1 = *reinterpret_cast<const float2*>(p + d0);
    float2 x2 = *reinterpret_cast<const float2*>(p + d0 + 64);
    float2 c  = *reinterpret_cast<const float2*>(cosT + t * HDIM + d0);
    float2 s  = *reinterpret_cast<const float2*>(sinT + t * HDIM + d0);

    float lo0 = x1.x * c.x - x2.x * s.x;
    float lo1 = x1.y * c.y - x2.y * s.y;
    float hi0 = x2.x * c.x + x1.x * s.x;
    float hi1 = x2.y * c.y + x1.y * s.y;

    int b = t >> 10;
    int tig = j & 3;
    int ktile = j >> 3;                            // d0>>4
    if (head < NH) {
        lo0 *= QSCALE; lo1 *= QSCALE; hi0 *= QSCALE; hi1 *= QSCALE;
        int qblk = (t & 1023) >> 7;
        int rLoc = t & 127, rb = rLoc >> 4, r16 = rLoc & 15;
        int reg = (((d0 & 15) >= 8) ? 2 : 0) + ((r16 >= 8) ? 1 : 0);
        int lane0 = (r16 & 7) * 4 + tig;
        uint32_t* dst = g_pq + ((size_t)((b * 8 + qblk) * 32 + head)) * 8192 + rb * 128;
        dst[ktile * 1024 + lane0 * 4 + reg]       = pack_h2(lo0, lo1);
        dst[(ktile + 4) * 1024 + lane0 * 4 + reg] = pack_h2(hi0, hi1);
    } else {
        int hkv = head - NH;
        int kvblk = (t & 1023) >> 6;
        int n = t & 63, nblk = n >> 3, nn = n & 7;
        int reg = ((d0 & 15) >= 8) ? 1 : 0;
        uint32_t* dst = g_pk + ((size_t)((b * 8 + hkv) * 16 + kvblk)) * 4096
                        + nblk * 64 + (nn * 4 + tig) * 2 + reg;
        dst[ktile * 512]       = pack_h2(lo0, lo1);
        dst[(ktile + 4) * 512] = pack_h2(hi0, hi1);
    }
}

// ---------------------------------------------------------------------------
// Kernel 2b: pack V (B-frag over k=kv, n=d; pairs adjacent tokens).
// g_pv layout: [b][hkv(8)][kvblk(16)][ktileV(4)][1024]
// ---------------------------------------------------------------------------
__global__ __launch_bounds__(256) void pack_v_kernel() {
    int idx = blockIdx.x * 256 + threadIdx.x;      // (T_TOK/2)*8*32
    int dq  = idx & 31;
    int hkv = (idx >> 5) & 7;
    int tp  = idx >> 8;                            // 0..1023
    int t   = tp * 2;
    int d0  = dq * 4;

    const float* Vg = g_qkv + (size_t)t * QKVC + (NH + NKV + hkv) * HDIM;
    float4 vlo = *reinterpret_cast<const float4*>(Vg + d0);
    float4 vhi = *reinterpret_cast<const float4*>(Vg + QKVC + d0);

    int b = t >> 10;
    int kvblk = (t & 1023) >> 6;
    int kc = t & 15;
    int tig = (kc >> 1) & 3;
    int reg = (kc >= 8) ? 1 : 0;
    int ktv = (t & 63) >> 4;
    uint32_t* dst = g_pv + ((size_t)((b * 8 + hkv) * 16 + kvblk)) * 4096 + ktv * 1024;
    float lo[4] = {vlo.x, vlo.y, vlo.z, vlo.w};
    float hi[4] = {vhi.x, vhi.y, vhi.z, vhi.w};
#pragma unroll
    for (int jj = 0; jj < 4; jj++) {
        int d = d0 + jj;
        int nblk = d >> 3, nn = d & 7;
        dst[nblk * 64 + (nn * 4 + tig) * 2 + reg] = pack_h2(lo[jj], hi[jj]);
    }
}

// ---------------------------------------------------------------------------
// Kernel 3: fp16 flash attention; Q and P register-resident, K/V via cp.async.
// CTA: 128 queries x 1 head, 256 threads. smem = 3 stages x (K 16KB + V 16KB).
// ---------------------------------------------------------------------------
#define ATTN_SMEM (3 * 8192 * 4)   // 98304

__global__ __launch_bounds__(256) void attn_tc_kernel(float* __restrict__ out) {
    extern __shared__ __align__(16) uint32_t sm[];
    const uint32_t smem_base = (uint32_t)__cvta_generic_to_shared(sm);

    const int tid  = threadIdx.x;
    const int wid  = tid >> 5;
    const int lane = tid & 31;
    const int gid  = lane >> 2;
    const int tig  = lane & 3;
    const int qrow = wid * 16;

    const int b   = blockIdx.y >> 5;
    const int h   = blockIdx.y & 31;
    const int kvh = h >> 2;
    const int q0  = blockIdx.x * 128;

    // Q fragments: register-resident for the whole kernel.
    const uint32_t* qbase = g_pq + ((size_t)((b * 8 + blockIdx.x) * 32 + h)) * 8192;
    uint4 qa[8];
#pragma unroll
    for (int ks = 0; ks < 8; ks++)
        qa[ks] = *reinterpret_cast<const uint4*>(qbase + ks * 1024 + wid * 128 + lane * 4);

    const uint32_t* kbase = g_pk + ((size_t)((b * 8 + kvh) * 16)) * 4096;
    const uint32_t* vbase = g_pv + ((size_t)((b * 8 + kvh) * 16)) * 4096;

#define AISSUE(kt, s)                                                          \
    do {                                                                       \
        uint32_t sa = smem_base + (uint32_t)(s) * 32768;                       \
        const uint32_t* gK = kbase + (size_t)(kt) * 4096;                      \
        const uint32_t* gV = vbase + (size_t)(kt) * 4096;                      \
        _Pragma("unroll")                                                      \
        for (int i = 0; i < 4; i++) {                                          \
            int c = tid + i * 256;                                             \
            cp_async16(sa + c * 16,         gK + c * 4);                       \
            cp_async16(sa + 16384 + c * 16, gV + c * 4);                       \
        }                                                                      \
    } while (0)

    float m[2] = {-1e30f, -1e30f}, l[2] = {0.f, 0.f};
    float oacc[16][4];
#pragma unroll
    for (int nb = 0; nb < 16; nb++)
#pragma unroll
        for (int c = 0; c < 4; c++) oacc[nb][c] = 0.f;

    const int ktiles = 2 * (blockIdx.x + 1);
    AISSUE(0, 0); CP_COMMIT();
    AISSUE(1, 1); CP_COMMIT();

    for (int kt = 0; kt < ktiles; kt++) {
        const int kv0 = kt * 64;
        CP_WAIT1();
        __syncthreads();
        // Refill: the stage (kt+2)%3 held tile kt-1, fully consumed last iter.
        if (kt + 2 < ktiles) AISSUE(kt + 2, (kt + 2) % 3);
        CP_COMMIT();   // unconditional: keeps wait_group accounting uniform

        const uint32_t* Kst = sm + (size_t)(kt % 3) * 8192;
        const uint32_t* Vst = Kst + 4096;

        // ---- S = Q K^T ----
        float sacc[8][4];
#pragma unroll
        for (int nb = 0; nb < 8; nb++)
#pragma unroll
            for (int c = 0; c < 4; c++) sacc[nb][c] = 0.f;

#pragma unroll
        for (int ks = 0; ks < 8; ks++) {
#pragma unroll
            for (int nb = 0; nb < 8; nb++) {
                uint2 bb = *reinterpret_cast<const uint2*>(
                    &Kst[ks * 512 + nb * 64 + (lane << 1)]);
                MMA_F16(sacc[nb], (reinterpret_cast<uint32_t*>(&qa[ks])),
                        (reinterpret_cast<uint32_t*>(&bb)));
            }
        }

        // Causal mask.
        const int row0 = q0 + qrow + gid;
        const int row1 = row0 + 8;
        if (kv0 + 63 > row0) {
#pragma unroll
            for (int nb = 0; nb < 8; nb++) {
                int c0 = kv0 + nb * 8 + 2 * tig;
                if (c0 > row0)     sacc[nb][0] = -1e30f;
                if (c0 + 1 > row0) sacc[nb][1] = -1e30f;
                if (c0 > row1)     sacc[nb][2] = -1e30f;
                if (c0 + 1 > row1) sacc[nb][3] = -1e30f;
            }
        }

        // ---- online softmax ----
#pragma unroll
        for (int r = 0; r < 2; r++) {
            float rmax = -1e30f;
#pragma unroll
            for (int nb = 0; nb < 8; nb++)
                rmax = fmaxf(rmax, fmaxf(sacc[nb][2 * r], sacc[nb][2 * r + 1]));
            rmax = fmaxf(rmax, __shfl_xor_sync(0xffffffffu, rmax, 1));
            rmax = fmaxf(rmax, __shfl_xor_sync(0xffffffffu, rmax, 2));
            float nm = fmaxf(m[r], rmax);
            float corr = __expf(m[r] - nm);
            float rs = 0.f;
#pragma unroll
            for (int nb = 0; nb < 8; nb++) {
                float p0 = __expf(sacc[nb][2 * r]     - nm);
                float p1 = __expf(sacc[nb][2 * r + 1] - nm);
                sacc[nb][2 * r] = p0; sacc[nb][2 * r + 1] = p1;
                rs += p0 + p1;
            }
            rs += __shfl_xor_sync(0xffffffffu, rs, 1);
            rs += __shfl_xor_sync(0xffffffffu, rs, 2);
            m[r] = nm;
            l[r] = l[r] * corr + rs;
#pragma unroll
            for (int nb = 0; nb < 16; nb++) {
                oacc[nb][2 * r]     *= corr;
                oacc[nb][2 * r + 1] *= corr;
            }
        }

        // ---- O += P V : P fragments built directly from sacc registers ----
#pragma unroll
        for (int kb = 0; kb < 4; kb++) {
            uint32_t a[4];
            a[0] = pack_h2(sacc[2 * kb][0],     sacc[2 * kb][1]);
            a[1] = pack_h2(sacc[2 * kb][2],     sacc[2 * kb][3]);
            a[2] = pack_h2(sacc[2 * kb + 1][0], sacc[2 * kb + 1][1]);
            a[3] = pack_h2(sacc[2 * kb + 1][2], sacc[2 * kb + 1][3]);
#pragma unroll
            for (int nb = 0; nb < 16; nb++) {
                uint2 bb = *reinterpret_cast<const uint2*>(
                    &Vst[kb * 1024 + nb * 64 + (lane << 1)]);
                MMA_F16(oacc[nb], a, (reinterpret_cast<uint32_t*>(&bb)));
            }
        }
        __syncthreads();   // all warps done with stage kt%3 before it is refilled
    }

    // Epilogue.
    const float inv0 = 1.f / l[0];
    const float inv1 = 1.f / l[1];
    const int t0 = b * SEQ + q0 + qrow + gid;
#pragma unroll
    for (int nb = 0; nb < 16; nb++) {
        int c = nb * 8 + 2 * tig;
        float2 v0 = {oacc[nb][0] * inv0, oacc[nb][1] * inv0};
        float2 v1 = {oacc[nb][2] * inv1, oacc[nb][3] * inv1};
        *reinterpret_cast<float2*>(out + (size_t)t0 * (NH * HDIM) + h * HDIM + c) = v0;
        *reinterpret_cast<float2*>(out + (size_t)(t0 + 8) * (NH * HDIM) + h * HDIM + c) = v1;
    }
}

// ---------------------------------------------------------------------------
extern "C" void kernel_launch(void* const* d_in, const int* in_sizes, int n_in,
                              void* d_out, int out_size) {
    const float* hidden = (const float*)d_in[0];
    const float* w_qkv  = (const float*)d_in[1];
    const float* cosT   = (const float*)d_in[2];
    const float* sinT   = (const float*)d_in[3];
    float* out = (float*)d_out;

    cudaFuncSetAttribute(gemm_f16_kernel, cudaFuncAttributeMaxDynamicSharedMemorySize, 98304);
    cudaFuncSetAttribute(attn_tc_kernel, cudaFuncAttributeMaxDynamicSharedMemorySize, ATTN_SMEM);

    pack_a_kernel<<<(T_TOK * DMODEL / 4) / 256, 256>>>(hidden);
    pack_w_kernel<<<(DMODEL / 2 * (QKVC / 4)) / 256, 256>>>(w_qkv);

    dim3 ggrid(QKVC / 128, T_TOK / 128);   // (48, 16)
    gemm_f16_kernel<<<ggrid, 256, 98304>>>();

    rope_pack_kernel<<<(T_TOK * 40 * 32) / 256, 256>>>(cosT, sinT);
    pack_v_kernel<<<((T_TOK / 2) * NKV * 32) / 256, 256>>>();

    dim3 agrid(SEQ / 128, NBATCH * NH);    // (8, 64)
    attn_tc_kernel<<<agrid, 256, ATTN_SMEM>>>(out);
}

// round 13
// speedup vs baseline: 1.3547x; 1.0139x over previous
#include <cuda_runtime.h>
#include <cuda_fp16.h>
#include <cstdint>

// Problem constants (B=2, S=1024, H=32, KVH=8, HD=128, DM=4096)
#define T_TOK   2048
#define DMODEL  4096
#define QKVC    6144
#define NH      32
#define NKV     8
#define HDIM    128
#define SEQ     1024
#define NBATCH  2
#define QSCALE  0.08838834764831845f

__device__ uint32_t g_qkvh[(size_t)T_TOK * QKVC / 2];      // GEMM output, fp16 half2
__device__ uint32_t g_pa[(size_t)T_TOK * DMODEL / 2];      // packed fp16 A tiles (GEMM)
__device__ uint32_t g_pb[(size_t)QKVC * DMODEL / 2];       // packed fp16 W tiles (GEMM)
__device__ uint32_t g_pq[(size_t)T_TOK * NH * HDIM / 2];   // Q A-frag tiles (post-rope)
__device__ uint32_t g_pk[(size_t)T_TOK * NKV * HDIM / 2];  // K B-frag tiles (post-rope)
__device__ uint32_t g_pv[(size_t)T_TOK * NKV * HDIM / 2];  // V B-frag tiles (transposed)

__device__ __forceinline__ uint32_t pack_h2(float lo, float hi) {
    __half2 h = __floats2half2_rn(lo, hi);
    return *reinterpret_cast<uint32_t*>(&h);
}
__device__ __forceinline__ float2 unpack_h2(uint32_t u) {
    __half2 h = *reinterpret_cast<__half2*>(&u);
    return __half22float2(h);
}

#define MMA_F16(d, a, b)                                                      \
    asm volatile(                                                             \
        "mma.sync.aligned.m16n8k16.row.col.f32.f16.f16.f32 "                  \
        "{%0,%1,%2,%3},{%4,%5,%6,%7},{%8,%9},{%0,%1,%2,%3};"                  \
        : "+f"(d[0]), "+f"(d[1]), "+f"(d[2]), "+f"(d[3])                      \
        : "r"(a[0]), "r"(a[1]), "r"(a[2]), "r"(a[3]), "r"(b[0]), "r"(b[1]))

__device__ __forceinline__ void cp_async16(uint32_t smem_addr, const void* gptr) {
    asm volatile("cp.async.cg.shared.global [%0], [%1], 16;"
                 :: "r"(smem_addr), "l"(gptr) : "memory");
}
#define CP_COMMIT() asm volatile("cp.async.commit_group;" ::: "memory")
#define CP_WAIT1()  asm volatile("cp.async.wait_group 1;" ::: "memory")

// ---------------------------------------------------------------------------
// Kernel 0a/0b: pack A and W for the GEMM (verified R9/R10 layouts).
// ---------------------------------------------------------------------------
__global__ __launch_bounds__(256) void pack_a_kernel(const float* __restrict__ A) {
    int i = blockIdx.x * 256 + threadIdx.x;
    int r  = i >> 10;
    int k0 = (i & 1023) << 2;
    float4 v = *reinterpret_cast<const float4*>(A + (size_t)r * DMODEL + k0);

    int mTile = r >> 7, rLoc = r & 127;
    int kTile = k0 >> 4, kLoc = k0 & 15;
    uint32_t* dst = g_pa + ((size_t)(mTile * (DMODEL / 16) + kTile)) * 1024;

    int rb = rLoc >> 4, r16 = rLoc & 15;
    int reg = ((kLoc >= 8) ? 2 : 0) + ((r16 >= 8) ? 1 : 0);
    int lane0 = (r16 & 7) * 4 + ((kLoc >> 1) & 3);
    int base = rb * 128;
    dst[base + lane0 * 4 + reg]       = pack_h2(v.x, v.y);
    dst[base + (lane0 + 1) * 4 + reg] = pack_h2(v.z, v.w);
}

__global__ __launch_bounds__(256) void pack_w_kernel(const float* __restrict__ W) {
    int i = blockIdx.x * 256 + threadIdx.x;
    int kp = i / 1536;
    int n0 = (i - kp * 1536) << 2;
    int k  = kp * 2;
    float4 vlo = *reinterpret_cast<const float4*>(W + (size_t)k * QKVC + n0);
    float4 vhi = *reinterpret_cast<const float4*>(W + (size_t)(k + 1) * QKVC + n0);

    int nTile = n0 >> 7, nLoc0 = n0 & 127;
    int kTile = k >> 4,  kLoc  = k & 15;
    uint32_t* dst = g_pb + ((size_t)(nTile * (DMODEL / 16) + kTile)) * 1024;

    int tig = (kLoc >> 1) & 3;
    int reg = (kLoc >= 8) ? 1 : 0;
    float lo[4] = {vlo.x, vlo.y, vlo.z, vlo.w};
    float hi[4] = {vhi.x, vhi.y, vhi.z, vhi.w};
#pragma unroll
    for (int j = 0; j < 4; j++) {
        int n = nLoc0 + j;
        int nblk = n >> 3, nn = n & 7;
        dst[nblk * 64 + (nn * 4 + tig) * 2 + reg] = pack_h2(lo[j], hi[j]);
    }
}

// ---------------------------------------------------------------------------
// Kernel 1: QKV GEMM (fp16 m16n8k16, BK=64, 3 stages, 96KB; fp16 epilogue).
// ---------------------------------------------------------------------------
__global__ __launch_bounds__(256, 2) void gemm_f16_kernel() {
    extern __shared__ __align__(16) uint32_t smem[];

    const int tid  = threadIdx.x;
    const int wid  = tid >> 5;
    const int lane = tid & 31;
    const int gid  = lane >> 2;
    const int tig  = lane & 3;
    const int wm   = wid >> 2;
    const int wn   = wid & 3;

    const uint32_t smem_base = (uint32_t)__cvta_generic_to_shared(smem);
    const uint32_t* pa = g_pa + (size_t)blockIdx.y * (DMODEL / 16) * 1024;
    const uint32_t* pb = g_pb + (size_t)blockIdx.x * (DMODEL / 16) * 1024;

    const int NCH = DMODEL / 64;

#define ISSUE(ch, s)                                                           \
    do {                                                                       \
        uint32_t sa = smem_base + (uint32_t)(s) * 32768;                       \
        const uint32_t* gA = pa + (size_t)(ch) * 4096 + tid * 4;               \
        const uint32_t* gB = pb + (size_t)(ch) * 4096 + tid * 4;               \
        cp_async16(sa + tid * 16,           gA);                               \
        cp_async16(sa + tid * 16 + 4096,    gA + 1024);                        \
        cp_async16(sa + tid * 16 + 8192,    gA + 2048);                        \
        cp_async16(sa + tid * 16 + 12288,   gA + 3072);                        \
        cp_async16(sa + 16384 + tid * 16,         gB);                         \
        cp_async16(sa + 16384 + tid * 16 + 4096,  gB + 1024);                  \
        cp_async16(sa + 16384 + tid * 16 + 8192,  gB + 2048);                  \
        cp_async16(sa + 16384 + tid * 16 + 12288, gB + 3072);                  \
    } while (0)

    float acc[4][4][4];
#pragma unroll
    for (int i = 0; i < 4; i++)
#pragma unroll
        for (int j = 0; j < 4; j++)
#pragma unroll
            for (int c = 0; c < 4; c++) acc[i][j][c] = 0.f;

    ISSUE(0, 0); CP_COMMIT();
    ISSUE(1, 1); CP_COMMIT();
    CP_WAIT1();
    __syncthreads();

    for (int ch = 0; ch < NCH; ch++) {
        if (ch + 2 < NCH) ISSUE(ch + 2, (ch + 2) % 3);
        CP_COMMIT();

        const uint32_t* St = smem + (size_t)(ch % 3) * 8192;

#pragma unroll
        for (int kt = 0; kt < 4; kt++) {
            const uint32_t* As = St + kt * 1024;
            const uint32_t* Bs = St + 4096 + kt * 1024;
            uint4 av[4];
            uint2 bv[4];
#pragma unroll
            for (int i = 0; i < 4; i++)
                av[i] = *reinterpret_cast<const uint4*>(
                    &As[((wm << 2) + i) * 128 + (lane << 2)]);
#pragma unroll
            for (int j = 0; j < 4; j++)
                bv[j] = *reinterpret_cast<const uint2*>(
                    &Bs[((wn << 2) + j) * 64 + (lane << 1)]);
#pragma unroll
            for (int i = 0; i < 4; i++)
#pragma unroll
                for (int j = 0; j < 4; j++)
                    MMA_F16(acc[i][j], (reinterpret_cast<uint32_t*>(&av[i])),
                            (reinterpret_cast<uint32_t*>(&bv[j])));
        }

        CP_WAIT1();
        __syncthreads();
    }

    // Epilogue: fp16 half2 words. Column pair index = wn*16 + j*4 + tig.
    uint32_t* C = g_qkvh + (size_t)blockIdx.y * 128 * (QKVC / 2) + blockIdx.x * 64;
#pragma unroll
    for (int i = 0; i < 4; i++) {
#pragma unroll
        for (int j = 0; j < 4; j++) {
            int r = wm * 64 + i * 16 + gid;
            int cp = wn * 16 + j * 4 + tig;
            C[(size_t)(r)     * (QKVC / 2) + cp] = pack_h2(acc[i][j][0], acc[i][j][1]);
            C[(size_t)(r + 8) * (QKVC / 2) + cp] = pack_h2(acc[i][j][2], acc[i][j][3]);
        }
    }
}

// ---------------------------------------------------------------------------
// Kernel 2 (fused): RoPE+pack Q/K, then pack V (block-range split).
// Q: g_pq [b][qblk(8)][h(32)][ktile(8)][1024]   (A-frag layout)
// K: g_pk [b][hkv(8)][kvblk(16)][ktile(8)][512] (B-frag layout)
// V: g_pv [b][hkv(8)][kvblk(16)][ktileV(4)][1024]
// ---------------------------------------------------------------------------
#define ROPE_BLOCKS 10240   // T_TOK*40*32/256
#define PACKV_BLOCKS 1024   // (T_TOK/2)*8*32/256

__global__ __launch_bounds__(256) void rope_packqkv_kernel(const float* __restrict__ cosT,
                                                           const float* __restrict__ sinT) {
    if (blockIdx.x < ROPE_BLOCKS) {
        int idx = blockIdx.x * 256 + threadIdx.x;      // T_TOK*40*32
        int j    = idx & 31;
        int head = (idx >> 5) % 40;
        int t    = idx / (32 * 40);
        int d0   = 2 * j;

        const uint32_t* p = g_qkvh + (size_t)t * (QKVC / 2) + head * 64;
        float2 x1 = unpack_h2(p[j]);         // d0, d0+1
        float2 x2 = unpack_h2(p[32 + j]);    // d0+64, d0+65
        float2 c  = *reinterpret_cast<const float2*>(cosT + t * HDIM + d0);
        float2 s  = *reinterpret_cast<const float2*>(sinT + t * HDIM + d0);

        float lo0 = x1.x * c.x - x2.x * s.x;
        float lo1 = x1.y * c.y - x2.y * s.y;
        float hi0 = x2.x * c.x + x1.x * s.x;
        float hi1 = x2.y * c.y + x1.y * s.y;

        int b = t >> 10;
        int tig = j & 3;
        int ktile = j >> 3;
        if (head < NH) {
            lo0 *= QSCALE; lo1 *= QSCALE; hi0 *= QSCALE; hi1 *= QSCALE;
            int qblk = (t & 1023) >> 7;
            int rLoc = t & 127, rb = rLoc >> 4, r16 = rLoc & 15;
            int reg = (((d0 & 15) >= 8) ? 2 : 0) + ((r16 >= 8) ? 1 : 0);
            int lane0 = (r16 & 7) * 4 + tig;
            uint32_t* dst = g_pq + ((size_t)((b * 8 + qblk) * 32 + head)) * 8192 + rb * 128;
            dst[ktile * 1024 + lane0 * 4 + reg]       = pack_h2(lo0, lo1);
            dst[(ktile + 4) * 1024 + lane0 * 4 + reg] = pack_h2(hi0, hi1);
        } else {
            int hkv = head - NH;
            int kvblk = (t & 1023) >> 6;
            int n = t & 63, nblk = n >> 3, nn = n & 7;
            int reg = ((d0 & 15) >= 8) ? 1 : 0;
            uint32_t* dst = g_pk + ((size_t)((b * 8 + hkv) * 16 + kvblk)) * 4096
                            + nblk * 64 + (nn * 4 + tig) * 2 + reg;
            dst[ktile * 512]       = pack_h2(lo0, lo1);
            dst[(ktile + 4) * 512] = pack_h2(hi0, hi1);
        }
    } else {
        int idx = (blockIdx.x - ROPE_BLOCKS) * 256 + threadIdx.x;  // (T_TOK/2)*8*32
        int dq  = idx & 31;
        int hkv = (idx >> 5) & 7;
        int tp  = idx >> 8;
        int t   = tp * 2;
        int d0  = dq * 4;

        const uint32_t* Vg = g_qkvh + (size_t)t * (QKVC / 2) + (NH + NKV + hkv) * 64 + (d0 >> 1);
        uint2 vlo = *reinterpret_cast<const uint2*>(Vg);                 // halves d0..d0+3, row t
        uint2 vhi = *reinterpret_cast<const uint2*>(Vg + (QKVC / 2));    // row t+1

        int b = t >> 10;
        int kvblk = (t & 1023) >> 6;
        int kc = t & 15;
        int tig = (kc >> 1) & 3;
        int reg = (kc >= 8) ? 1 : 0;
        int ktv = (t & 63) >> 4;
        uint32_t* dst = g_pv + ((size_t)((b * 8 + hkv) * 16 + kvblk)) * 4096 + ktv * 1024;

        // Output word for dim d combines half(d) of row t (lo) and row t+1 (hi).
        uint32_t w[4];
        w[0] = __byte_perm(vlo.x, vhi.x, 0x5410);
        w[1] = __byte_perm(vlo.x, vhi.x, 0x7632);
        w[2] = __byte_perm(vlo.y, vhi.y, 0x5410);
        w[3] = __byte_perm(vlo.y, vhi.y, 0x7632);
#pragma unroll
        for (int jj = 0; jj < 4; jj++) {
            int d = d0 + jj;
            int nblk = d >> 3, nn = d & 7;
            dst[nblk * 64 + (nn * 4 + tig) * 2 + reg] = w[jj];
        }
    }
}

// ---------------------------------------------------------------------------
// Kernel 3: fp16 flash attention; Q and P register-resident, K/V via cp.async.
// One barrier per tile (top-of-loop barrier covers the stage-reuse hazard).
// ---------------------------------------------------------------------------
#define ATTN_SMEM (3 * 8192 * 4)   // 98304

__global__ __launch_bounds__(256) void attn_tc_kernel(float* __restrict__ out) {
    extern __shared__ __align__(16) uint32_t sm[];
    const uint32_t smem_base = (uint32_t)__cvta_generic_to_shared(sm);

    const int tid  = threadIdx.x;
    const int wid  = tid >> 5;
    const int lane = tid & 31;
    const int gid  = lane >> 2;
    const int tig  = lane & 3;
    const int qrow = wid * 16;

    const int b   = blockIdx.y >> 5;
    const int h   = blockIdx.y & 31;
    const int kvh = h >> 2;
    const int q0  = blockIdx.x * 128;

    const uint32_t* qbase = g_pq + ((size_t)((b * 8 + blockIdx.x) * 32 + h)) * 8192;
    uint4 qa[8];
#pragma unroll
    for (int ks = 0; ks < 8; ks++)
        qa[ks] = *reinterpret_cast<const uint4*>(qbase + ks * 1024 + wid * 128 + lane * 4);

    const uint32_t* kbase = g_pk + ((size_t)((b * 8 + kvh) * 16)) * 4096;
    const uint32_t* vbase = g_pv + ((size_t)((b * 8 + kvh) * 16)) * 4096;

#define AISSUE(kt, s)                                                          \
    do {                                                                       \
        uint32_t sa = smem_base + (uint32_t)(s) * 32768;                       \
        const uint32_t* gK = kbase + (size_t)(kt) * 4096;                      \
        const uint32_t* gV = vbase + (size_t)(kt) * 4096;                      \
        _Pragma("unroll")                                                      \
        for (int i = 0; i < 4; i++) {                                          \
            int c = tid + i * 256;                                             \
            cp_async16(sa + c * 16,         gK + c * 4);                       \
            cp_async16(sa + 16384 + c * 16, gV + c * 4);                       \
        }                                                                      \
    } while (0)

    float m[2] = {-1e30f, -1e30f}, l[2] = {0.f, 0.f};
    float oacc[16][4];
#pragma unroll
    for (int nb = 0; nb < 16; nb++)
#pragma unroll
        for (int c = 0; c < 4; c++) oacc[nb][c] = 0.f;

    const int ktiles = 2 * (blockIdx.x + 1);
    AISSUE(0, 0); CP_COMMIT();
    AISSUE(1, 1); CP_COMMIT();

    for (int kt = 0; kt < ktiles; kt++) {
        const int kv0 = kt * 64;
        CP_WAIT1();
        __syncthreads();   // (a) data of tile kt visible; (b) all warps done iter kt-1
        if (kt + 2 < ktiles) AISSUE(kt + 2, (kt + 2) % 3);
        CP_COMMIT();

        const uint32_t* Kst = sm + (size_t)(kt % 3) * 8192;
        const uint32_t* Vst = Kst + 4096;

        // ---- S = Q K^T ----
        float sacc[8][4];
#pragma unroll
        for (int nb = 0; nb < 8; nb++)
#pragma unroll
            for (int c = 0; c < 4; c++) sacc[nb][c] = 0.f;

#pragma unroll
        for (int ks = 0; ks < 8; ks++) {
#pragma unroll
            for (int nb = 0; nb < 8; nb++) {
                uint2 bb = *reinterpret_cast<const uint2*>(
                    &Kst[ks * 512 + nb * 64 + (lane << 1)]);
                MMA_F16(sacc[nb], (reinterpret_cast<uint32_t*>(&qa[ks])),
                        (reinterpret_cast<uint32_t*>(&bb)));
            }
        }

        // Causal mask.
        const int row0 = q0 + qrow + gid;
        const int row1 = row0 + 8;
        if (kv0 + 63 > row0) {
#pragma unroll
            for (int nb = 0; nb < 8; nb++) {
                int c0 = kv0 + nb * 8 + 2 * tig;
                if (c0 > row0)     sacc[nb][0] = -1e30f;
                if (c0 + 1 > row0) sacc[nb][1] = -1e30f;
                if (c0 > row1)     sacc[nb][2] = -1e30f;
                if (c0 + 1 > row1) sacc[nb][3] = -1e30f;
            }
        }

        // ---- online softmax ----
#pragma unroll
        for (int r = 0; r < 2; r++) {
            float rmax = -1e30f;
#pragma unroll
            for (int nb = 0; nb < 8; nb++)
                rmax = fmaxf(rmax, fmaxf(sacc[nb][2 * r], sacc[nb][2 * r + 1]));
            rmax = fmaxf(rmax, __shfl_xor_sync(0xffffffffu, rmax, 1));
            rmax = fmaxf(rmax, __shfl_xor_sync(0xffffffffu, rmax, 2));
            float nm = fmaxf(m[r], rmax);
            float corr = __expf(m[r] - nm);
            float rs = 0.f;
#pragma unroll
            for (int nb = 0; nb < 8; nb++) {
                float p0 = __expf(sacc[nb][2 * r]     - nm);
                float p1 = __expf(sacc[nb][2 * r + 1] - nm);
                sacc[nb][2 * r] = p0; sacc[nb][2 * r + 1] = p1;
                rs += p0 + p1;
            }
            rs += __shfl_xor_sync(0xffffffffu, rs, 1);
            rs += __shfl_xor_sync(0xffffffffu, rs, 2);
            m[r] = nm;
            l[r] = l[r] * corr + rs;
#pragma unroll
            for (int nb = 0; nb < 16; nb++) {
                oacc[nb][2 * r]     *= corr;
                oacc[nb][2 * r + 1] *= corr;
            }
        }

        // ---- O += P V ----
#pragma unroll
        for (int kb = 0; kb < 4; kb++) {
            uint32_t a[4];
            a[0] = pack_h2(sacc[2 * kb][0],     sacc[2 * kb][1]);
            a[1] = pack_h2(sacc[2 * kb][2],     sacc[2 * kb][3]);
            a[2] = pack_h2(sacc[2 * kb + 1][0], sacc[2 * kb + 1][1]);
            a[3] = pack_h2(sacc[2 * kb + 1][2], sacc[2 * kb + 1][3]);
#pragma unroll
            for (int nb = 0; nb < 16; nb++) {
                uint2 bb = *reinterpret_cast<const uint2*>(
                    &Vst[kb * 1024 + nb * 64 + (lane << 1)]);
                MMA_F16(oacc[nb], a, (reinterpret_cast<uint32_t*>(&bb)));
            }
        }
    }

    // Epilogue.
    const float inv0 = 1.f / l[0];
    const float inv1 = 1.f / l[1];
    const int t0 = b * SEQ + q0 + qrow + gid;
#pragma unroll
    for (int nb = 0; nb < 16; nb++) {
        int c = nb * 8 + 2 * tig;
        float2 v0 = {oacc[nb][0] * inv0, oacc[nb][1] * inv0};
        float2 v1 = {oacc[nb][2] * inv1, oacc[nb][3] * inv1};
        *reinterpret_cast<float2*>(out + (size_t)t0 * (NH * HDIM) + h * HDIM + c) = v0;
        *reinterpret_cast<float2*>(out + (size_t)(t0 + 8) * (NH * HDIM) + h * HDIM + c) = v1;
    }
}

// ---------------------------------------------------------------------------
extern "C" void kernel_launch(void* const* d_in, const int* in_sizes, int n_in,
                              void* d_out, int out_size) {
    const float* hidden = (const float*)d_in[0];
    const float* w_qkv  = (const float*)d_in[1];
    const float* cosT   = (const float*)d_in[2];
    const float* sinT   = (const float*)d_in[3];
    float* out = (float*)d_out;

    cudaFuncSetAttribute(gemm_f16_kernel, cudaFuncAttributeMaxDynamicSharedMemorySize, 98304);
    cudaFuncSetAttribute(attn_tc_kernel, cudaFuncAttributeMaxDynamicSharedMemorySize, ATTN_SMEM);

    pack_a_kernel<<<(T_TOK * DMODEL / 4) / 256, 256>>>(hidden);
    pack_w_kernel<<<(DMODEL / 2 * (QKVC / 4)) / 256, 256>>>(w_qkv);

    dim3 ggrid(QKVC / 128, T_TOK / 128);   // (48, 16)
    gemm_f16_kernel<<<ggrid, 256, 98304>>>();

    rope_packqkv_kernel<<<ROPE_BLOCKS + PACKV_BLOCKS, 256>>>(cosT, sinT);

    dim3 agrid(SEQ / 128, NBATCH * NH);    // (8, 64)
    attn_tc_kernel<<<agrid, 256, ATTN_SMEM>>>(out);
}